// round 14
// baseline (speedup 1.0000x reference)
#include <cuda_runtime.h>
#include <cuda_bf16.h>

// BayesianMF: per-user Bayesian linear update
//   prec_u = lambda_K + alpha * sum_{j in obs(u)} V_j V_j^T
//   rhs_u  = alpha * sum_j r_j V_j + lambda_K @ mu_K
//   mu_u   = prec_u^{-1} rhs_u ;  L_u = chol(prec_u^{-1}) ; out = mu + L z
//
// chol(P^{-1}) identity: J = reversal permutation, Q = J P J, H = chol(Q).
// Then L = J H^{-T} J = chol(P^{-1}), so L z = J H^{-T} (J z): one backward
// substitution, no explicit inverse, no second Cholesky.
//
// R14 = R13 + ONE change (accum): all shuffles replaced by 2x LDG.64 of the
// lane's two operand pairs (indices are consecutive even-based pairs), score
// entries moved to diag-Q lanes 4..7 (4 each, float4 writeback).
// MIO ops/obs: 6 -> 3 (accum measured MIO-bound: R12's equal-MIO variant
// was neutral).

#define D          16
#define NTRI       136          // 16*17/2
#define ACC_STRIDE 152          // 136 outer + 16 scoresum
#define MAX_USERS  50016
#define NNZ_MAX    1048576
#define ALPHA_F    2.0f
#define FULLM      0xffffffffu

#define TRI(i, j) (((i) * ((i) + 1)) / 2 + (j))

// Scratch (no cudaMalloc allowed). Zero-initialized at module load;
// scanC re-zeroes g_counts each run so graph replays stay correct.
__device__ __align__(16) float g_acc[(size_t)MAX_USERS * ACC_STRIDE];  // 30.4 MB
__device__ int  g_counts[MAX_USERS];
__device__ int  g_offsets[MAX_USERS + 1];
__device__ int  g_cursors[MAX_USERS];
__device__ int  g_blocksums[256];
__device__ int2 g_sorted[NNZ_MAX];                                     // 8 MB

// ---------------------------------------------------------------------------
// Phase 1a: histogram of user_ids (4 obs per thread, vector loads)
// ---------------------------------------------------------------------------
__global__ void hist_kernel(const int* __restrict__ user_ids, int nnz) {
    const int i4 = (blockIdx.x * blockDim.x + threadIdx.x) * 4;
    if (i4 + 3 < nnz) {
        const int4 u = *reinterpret_cast<const int4*>(user_ids + i4);
        atomicAdd(&g_counts[u.x], 1);
        atomicAdd(&g_counts[u.y], 1);
        atomicAdd(&g_counts[u.z], 1);
        atomicAdd(&g_counts[u.w], 1);
    } else {
        for (int i = i4; i < nnz; i++) atomicAdd(&g_counts[user_ids[i]], 1);
    }
}

// ---------------------------------------------------------------------------
// Phase 1b: parallel exclusive scan, 3 kernels.
// ---------------------------------------------------------------------------
__global__ void scanA_kernel(int num_users) {
    __shared__ int sh[256];
    const int tid = threadIdx.x;
    const int i = blockIdx.x * 256 + tid;
    int v = (i < num_users) ? g_counts[i] : 0;
    sh[tid] = v;
    __syncthreads();
#pragma unroll
    for (int off = 128; off > 0; off >>= 1) {
        if (tid < off) sh[tid] += sh[tid + off];
        __syncthreads();
    }
    if (tid == 0) g_blocksums[blockIdx.x] = sh[0];
}

__global__ void scanB_kernel(int nblocks, int num_users) {
    __shared__ int sh[256];
    const int tid = threadIdx.x;
    int v = (tid < nblocks) ? g_blocksums[tid] : 0;
    sh[tid] = v;
    __syncthreads();
#pragma unroll
    for (int off = 1; off < 256; off <<= 1) {
        int val = (tid >= off) ? sh[tid - off] : 0;
        __syncthreads();
        sh[tid] += val;
        __syncthreads();
    }
    if (tid < nblocks) g_blocksums[tid] = sh[tid] - v;     // exclusive
    if (tid == nblocks - 1) g_offsets[num_users] = sh[tid]; // sentinel = nnz
}

__global__ void scanC_kernel(int num_users) {
    __shared__ int sh[256];
    const int tid = threadIdx.x;
    const int i = blockIdx.x * 256 + tid;
    int v = (i < num_users) ? g_counts[i] : 0;
    sh[tid] = v;
    __syncthreads();
#pragma unroll
    for (int off = 1; off < 256; off <<= 1) {
        int val = (tid >= off) ? sh[tid - off] : 0;
        __syncthreads();
        sh[tid] += val;
        __syncthreads();
    }
    if (i < num_users) {
        const int excl = sh[tid] - v + g_blocksums[blockIdx.x];
        g_offsets[i] = excl;
        g_cursors[i] = excl;
        g_counts[i] = 0;                  // self-clean for next replay
    }
}

// ---------------------------------------------------------------------------
// Phase 1c: bucket observations into CSR order (4 obs per thread)
// ---------------------------------------------------------------------------
__global__ void bucket_kernel(const int*   __restrict__ user_ids,
                              const int*   __restrict__ item_ids,
                              const float* __restrict__ ratings,
                              int nnz) {
    const int i4 = (blockIdx.x * blockDim.x + threadIdx.x) * 4;
    if (i4 + 3 < nnz) {
        const int4   u = *reinterpret_cast<const int4*>(user_ids + i4);
        const int4   it = *reinterpret_cast<const int4*>(item_ids + i4);
        const float4 r = *reinterpret_cast<const float4*>(ratings + i4);
        int p0 = atomicAdd(&g_cursors[u.x], 1);
        int p1 = atomicAdd(&g_cursors[u.y], 1);
        int p2 = atomicAdd(&g_cursors[u.z], 1);
        int p3 = atomicAdd(&g_cursors[u.w], 1);
        g_sorted[p0] = make_int2(it.x, __float_as_int(r.x));
        g_sorted[p1] = make_int2(it.y, __float_as_int(r.y));
        g_sorted[p2] = make_int2(it.z, __float_as_int(r.z));
        g_sorted[p3] = make_int2(it.w, __float_as_int(r.w));
    } else {
        for (int i = i4; i < nnz; i++) {
            int pos = atomicAdd(&g_cursors[user_ids[i]], 1);
            g_sorted[pos] = make_int2(item_ids[i], __float_as_int(ratings[i]));
        }
    }
}

// ---------------------------------------------------------------------------
// Phase 2: ONE WARP PER BLOCK accumulation, SHUFFLE-FREE.
// Clique decomposition of the 136-entry lower triangle:
//   lanes 0..3  ("TT"): two 2x2 triangles (6 entries) from pairs
//                       (v[4t],v[4t+1]) and (v[4t+2],v[4t+3])
//   lanes 4..31 ("Q") : one 2x2 block (4 entries) from pairs
//                       (v[i0],v[i0+1]) and (v[k0],v[k0+1]); i0,k0 even
//   lanes 4..7 (diag Q, c=lane-4): also carry 4 score entries r*v[4c..4c+3]
//                       (they load exactly those values), float4 writeback.
// Per obs: 1 uniform LDG (obs) + 2 LDG.64 (V pairs) = 3 MIO ops, 0 SHFL.
// ---------------------------------------------------------------------------
__global__ void __launch_bounds__(32)
accum_kernel(const float* __restrict__ V, int num_users) {
    const int gw   = blockIdx.x;
    const int lane = threadIdx.x;
    if (gw >= num_users) return;

    const int start = __ldg(&g_offsets[gw]);
    const int n     = __ldg(&g_offsets[gw + 1]) - start;

    const bool isTT = (lane < 4);
    int s0, s2;                  // even base indices of the two operand pairs
    int d0, d1, d2, d3, d4, d5;  // destination offsets in acc row

    if (isTT) {
        const int t = lane;
        s0 = 4 * t;       // pair (v[4t], v[4t+1])
        s2 = 4 * t + 2;   // pair (v[4t+2], v[4t+3])
        d0 = TRI(4 * t,     4 * t);
        d1 = TRI(4 * t + 1, 4 * t);
        d2 = TRI(4 * t + 1, 4 * t + 1);
        d3 = TRI(4 * t + 2, 4 * t + 2);
        d4 = TRI(4 * t + 3, 4 * t + 2);
        d5 = TRI(4 * t + 3, 4 * t + 3);
    } else {
        const int c = lane - 4;
        int i0, k0;
        if (c < 4) {                      // diag block lower-left 2x2
            i0 = 4 * c + 2; k0 = 4 * c;
        } else {                          // off-diag block quadrant
            const int c2 = c - 4;
            const int m = c2 >> 2, q = c2 & 3;
            // (A,B) for m = 0..5: (0,1),(0,2),(0,3),(1,2),(1,3),(2,3)
            const int A = (m < 3) ? 0 : ((m < 5) ? 1 : 2);
            const int B = (m < 3) ? (m + 1) : ((m < 5) ? (m - 1) : 3);
            i0 = 4 * B + 2 * (q >> 1);
            k0 = 4 * A + 2 * (q & 1);
        }
        const int i1 = i0 + 1, k1 = k0 + 1;
        s0 = i0;          // pair (v[i0], v[i1])
        s2 = k0;          // pair (v[k0], v[k1])
        d0 = TRI(i0, k0); d1 = TRI(i0, k1);
        d2 = TRI(i1, k0); d3 = TRI(i1, k1);
        d4 = 0; d5 = 0;
    }
    const bool isDiagQ = (lane >= 4 && lane < 8);   // score carriers

    float a0 = 0.f, a1 = 0.f, a2 = 0.f, a3 = 0.f, a4 = 0.f, a5 = 0.f;
    float sc0 = 0.f, sc1 = 0.f, sc2 = 0.f, sc3 = 0.f;

#pragma unroll 4
    for (int t = 0; t < n; t++) {
        const int2  ob = __ldg(&g_sorted[start + t]);   // uniform broadcast
        const float r  = __int_as_float(ob.y);
        const float* Vr = V + ((size_t)(unsigned)ob.x << 4);
        const float2 pa = __ldg(reinterpret_cast<const float2*>(Vr + s0));
        const float2 pb = __ldg(reinterpret_cast<const float2*>(Vr + s2));
        if (isTT) {
            a0 += pa.x * pa.x; a1 += pa.y * pa.x; a2 += pa.y * pa.y;
            a3 += pb.x * pb.x; a4 += pb.y * pb.x; a5 += pb.y * pb.y;
        } else {
            a0 += pa.x * pb.x; a1 += pa.x * pb.y;
            a2 += pa.y * pb.x; a3 += pa.y * pb.y;
            // scores (only diag-Q lanes write these back):
            // pb = (v[4c], v[4c+1]), pa = (v[4c+2], v[4c+3])
            sc0 += r * pb.x; sc1 += r * pb.y;
            sc2 += r * pa.x; sc3 += r * pa.y;
        }
    }

    float* acc = g_acc + (size_t)gw * ACC_STRIDE;
    if (isTT) {
        acc[d0] = a0; acc[d1] = a1; acc[d2] = a2;
        acc[d3] = a3; acc[d4] = a4; acc[d5] = a5;
    } else {
        acc[d0] = a0; acc[d1] = a1; acc[d2] = a2; acc[d3] = a3;
        if (isDiagQ) {
            // score[4c + 0..3] at NTRI + 4c; 136*4 B base is 16B-aligned.
            const int c = lane - 4;
            *reinterpret_cast<float4*>(acc + NTRI + 4 * c) =
                make_float4(sc0, sc1, sc2, sc3);
        }
    }
}

// ---------------------------------------------------------------------------
// Phase 3: per-user dense solve (R13 verbatim: vector row ingest + R5 math)
// ---------------------------------------------------------------------------
__global__ void __launch_bounds__(128, 2)
solve_kernel(const float* __restrict__ lambdaK,
             const float* __restrict__ muK,
             const float* __restrict__ z,
             float*       __restrict__ out,
             int num_users) {
    int u = blockIdx.x * blockDim.x + threadIdx.x;
    if (u >= num_users) return;

    // Vector ingest of this user's 608B accumulator row.
    float Sl[ACC_STRIDE];
    {
        const float4* S4 = reinterpret_cast<const float4*>(
            g_acc + (size_t)u * ACC_STRIDE);
        float4* B4 = reinterpret_cast<float4*>(Sl);
#pragma unroll
        for (int i = 0; i < ACC_STRIDE / 4; i++) B4[i] = __ldg(&S4[i]);
    }
    const float* S = Sl;

    // Q = J * prec * J, packed lower (i >= j)
    float H[NTRI];
#pragma unroll
    for (int i = 0; i < D; i++) {
#pragma unroll
        for (int j = 0; j <= i; j++) {
            const int a = 15 - i, b = 15 - j;   // b >= a
            H[TRI(i, j)] = __ldg(&lambdaK[a * D + b]) + ALPHA_F * S[TRI(b, a)];
        }
    }

    // Reversed rhs: w[i] = rhs[15-i]
    float w[D];
#pragma unroll
    for (int i = 0; i < D; i++) {
        const int a = 15 - i;
        float t = ALPHA_F * S[NTRI + a];
#pragma unroll
        for (int b = 0; b < D; b++) {
            t += __ldg(&lambdaK[a * D + b]) * __ldg(&muK[b]);
        }
        w[i] = t;
    }

    // In-place Cholesky of Q
    float dinv[D];
#pragma unroll
    for (int j = 0; j < D; j++) {
        float s = H[TRI(j, j)];
#pragma unroll
        for (int k = 0; k < j; k++) {
            const float g = H[TRI(j, k)];
            s -= g * g;
        }
        const float sq = sqrtf(s);
        const float rj = 1.0f / sq;
        H[TRI(j, j)] = sq;
        dinv[j] = rj;
#pragma unroll
        for (int i = j + 1; i < D; i++) {
            float t = H[TRI(i, j)];
#pragma unroll
            for (int k = 0; k < j; k++) {
                t -= H[TRI(i, k)] * H[TRI(j, k)];
            }
            H[TRI(i, j)] = t * rj;
        }
    }

    // Solve Q x = w: forward then backward, in place. mu[a] = w[15-a].
#pragma unroll
    for (int i = 0; i < D; i++) {
        float t = w[i];
#pragma unroll
        for (int k = 0; k < i; k++) t -= H[TRI(i, k)] * w[k];
        w[i] = t * dinv[i];
    }
#pragma unroll
    for (int i = D - 1; i >= 0; i--) {
        float t = w[i];
#pragma unroll
        for (int k = D - 1; k > i; k--) t -= H[TRI(k, i)] * w[k];
        w[i] = t * dinv[i];
    }

    // Sample term: L z = J H^{-T} (J z); one backward substitution.
    const float4* zr = reinterpret_cast<const float4*>(z + (size_t)u * D);
    float4 z0 = zr[0], z1 = zr[1], z2 = zr[2], z3 = zr[3];
    float zf[D] = {z0.x, z0.y, z0.z, z0.w, z1.x, z1.y, z1.z, z1.w,
                   z2.x, z2.y, z2.z, z2.w, z3.x, z3.y, z3.z, z3.w};
    float s[D];
#pragma unroll
    for (int i = 0; i < D; i++) s[i] = zf[15 - i];   // Jz
#pragma unroll
    for (int i = D - 1; i >= 0; i--) {
        float t = s[i];
#pragma unroll
        for (int k = D - 1; k > i; k--) t -= H[TRI(k, i)] * s[k];
        s[i] = t * dinv[i];
    }

    // out[a] = mu[a] + (Lz)[a] = w[15-a] + s[15-a]
    float4* o = reinterpret_cast<float4*>(out + (size_t)u * D);
    float r0[D];
#pragma unroll
    for (int a = 0; a < D; a++) r0[a] = w[15 - a] + s[15 - a];
    o[0] = make_float4(r0[0],  r0[1],  r0[2],  r0[3]);
    o[1] = make_float4(r0[4],  r0[5],  r0[6],  r0[7]);
    o[2] = make_float4(r0[8],  r0[9],  r0[10], r0[11]);
    o[3] = make_float4(r0[12], r0[13], r0[14], r0[15]);
}

// ---------------------------------------------------------------------------
extern "C" void kernel_launch(void* const* d_in, const int* in_sizes, int n_in,
                              void* d_out, int out_size) {
    const float* V       = (const float*)d_in[0];
    const float* ratings = (const float*)d_in[1];
    const float* muK     = (const float*)d_in[2];
    const float* lambdaK = (const float*)d_in[3];
    const float* z       = (const float*)d_in[4];
    const int*   uid     = (const int*)d_in[5];
    const int*   iid     = (const int*)d_in[6];

    const int nnz       = in_sizes[5];        // user_ids length
    const int num_users = in_sizes[4] / D;    // z is [U, 16]

    const int q = (nnz + 3) / 4;              // 4 obs per thread
    const int nchunks = (num_users + 255) / 256;  // 196 <= 256

    hist_kernel<<<(q + 255) / 256, 256>>>(uid, nnz);
    scanA_kernel<<<nchunks, 256>>>(num_users);
    scanB_kernel<<<1, 256>>>(nchunks, num_users);
    scanC_kernel<<<nchunks, 256>>>(num_users);
    bucket_kernel<<<(q + 255) / 256, 256>>>(uid, iid, ratings, nnz);

    accum_kernel<<<num_users, 32>>>(V, num_users);

    solve_kernel<<<(num_users + 127) / 128, 128>>>(lambdaK, muK, z,
                                                   (float*)d_out, num_users);
}